// round 2
// baseline (speedup 1.0000x reference)
#include <cuda_runtime.h>
#include <math.h>

// ---------------------------------------------------------------------------
// NaN-interpolation, [1, 2M, 16] f32. Single persistent kernel:
//   phase A: per-column masked sum/count (forward order), per-block partials
//   grid-sync; block 0 reduces partials -> g_mean; grid-sync
//   phase B: fill NaNs with column mean (reverse order, streaming ld/st,
//            exploiting the L2-resident tail left by phase A)
// Grid = exactly one resident wave (148 SMs x 8 blocks x 256 thr) so the
// software grid barrier cannot deadlock; __launch_bounds__(256, 8) forces
// regs <= 32 to guarantee 8 blocks/SM.
// ---------------------------------------------------------------------------

#define COLS     16
#define NBLOCKS  (148 * 8)        // 1184 = one full wave
#define NTHREADS 256

__device__ float g_part_sum[NBLOCKS][COLS];
__device__ float g_part_cnt[NBLOCKS][COLS];
__device__ float g_mean[COLS];
__device__ unsigned long long g_ctr;   // zero-init at module load; monotonic across replays

__device__ __forceinline__ void grid_sync() {
    __threadfence();
    __syncthreads();
    if (threadIdx.x == 0) {
        unsigned long long old = atomicAdd(&g_ctr, 1ULL);
        unsigned long long target = old - (old % NBLOCKS) + NBLOCKS;
        unsigned long long cur;
        for (;;) {
            asm volatile("ld.global.acquire.gpu.u64 %0, [%1];"
                         : "=l"(cur) : "l"(&g_ctr));
            if (cur >= target) break;
            __nanosleep(128);
        }
    }
    __syncthreads();
}

__global__ void __launch_bounds__(NTHREADS, 8) interp_fused_kernel(
    const float4* __restrict__ in, float4* __restrict__ out, int n4)
{
    __shared__ float s_sum[COLS];
    __shared__ float s_cnt[COLS];
    __shared__ float sh_s[NTHREADS];
    __shared__ float sh_n[NTHREADS];

    const int t      = threadIdx.x;
    const int idx    = blockIdx.x * NTHREADS + t;
    const int stride = NBLOCKS * NTHREADS;    // multiple of 4 -> (v & 3) constant
    const int g      = idx & 3;               // column group: cols 4g..4g+3

    // ---------------- Phase A: masked reduce ----------------
    if (t < COLS) { s_sum[t] = 0.0f; s_cnt[t] = 0.0f; }
    __syncthreads();

    float s0 = 0.f, s1 = 0.f, s2 = 0.f, s3 = 0.f;
    float c0 = 0.f, c1 = 0.f, c2 = 0.f, c3 = 0.f;

    for (int v = idx; v < n4; v += stride) {
        float4 x = in[v];
        bool v0 = (x.x == x.x), v1 = (x.y == x.y), v2 = (x.z == x.z), v3 = (x.w == x.w);
        s0 += v0 ? x.x : 0.0f;  c0 += v0 ? 1.0f : 0.0f;
        s1 += v1 ? x.y : 0.0f;  c1 += v1 ? 1.0f : 0.0f;
        s2 += v2 ? x.z : 0.0f;  c2 += v2 ? 1.0f : 0.0f;
        s3 += v3 ? x.w : 0.0f;  c3 += v3 ? 1.0f : 0.0f;
    }

    atomicAdd(&s_sum[4 * g + 0], s0);  atomicAdd(&s_cnt[4 * g + 0], c0);
    atomicAdd(&s_sum[4 * g + 1], s1);  atomicAdd(&s_cnt[4 * g + 1], c1);
    atomicAdd(&s_sum[4 * g + 2], s2);  atomicAdd(&s_cnt[4 * g + 2], c2);
    atomicAdd(&s_sum[4 * g + 3], s3);  atomicAdd(&s_cnt[4 * g + 3], c3);
    __syncthreads();

    if (t < COLS) {
        g_part_sum[blockIdx.x][t] = s_sum[t];
        g_part_cnt[blockIdx.x][t] = s_cnt[t];
    }

    grid_sync();   // partials visible everywhere

    // ---------------- block 0: fold partials -> g_mean ----------------
    if (blockIdx.x == 0) {
        const int c = t & 15;                 // column
        float S = 0.f, N = 0.f;
        for (int j = t >> 4; j < NBLOCKS; j += NTHREADS / 16) {  // 74 partials each
            S += g_part_sum[j][c];
            N += g_part_cnt[j][c];
        }
        sh_s[t] = S; sh_n[t] = N;
        __syncthreads();
        if (t < COLS) {
            float SS = 0.f, NN = 0.f;
            #pragma unroll
            for (int k = 0; k < NTHREADS / 16; k++) {
                SS += sh_s[k * 16 + t];
                NN += sh_n[k * 16 + t];
            }
            g_mean[t] = SS / fmaxf(NN, 1.0f);
        }
    }

    grid_sync();   // g_mean visible everywhere

    // ---------------- Phase B: fill (reverse order) ----------------
    float m0, m1, m2, m3;
    m0 = __ldcg(&g_mean[4 * g + 0]);
    m1 = __ldcg(&g_mean[4 * g + 1]);
    m2 = __ldcg(&g_mean[4 * g + 2]);
    m3 = __ldcg(&g_mean[4 * g + 3]);

    if (idx < n4) {
        // Largest v congruent to idx (mod stride): walk backward so we start
        // in the L2-resident tail left by Phase A (128 MB data vs ~126 MB L2).
        int v = idx + ((n4 - 1 - idx) / stride) * stride;
        for (; v >= 0; v -= stride) {
            float4 x = __ldcs(&in[v]);     // evict-first after use
            float4 o;
            o.x = (x.x == x.x) ? x.x : m0;
            o.y = (x.y == x.y) ? x.y : m1;
            o.z = (x.z == x.z) ? x.z : m2;
            o.w = (x.w == x.w) ? x.w : m3;
            __stcs(&out[v], o);            // streaming store: keep input cached
        }
    }
}

extern "C" void kernel_launch(void* const* d_in, const int* in_sizes, int n_in,
                              void* d_out, int out_size)
{
    const float4* in  = (const float4*)d_in[0];
    float4*       out = (float4*)d_out;
    int n4 = in_sizes[0] / 4;   // 32,000,000 / 4 = 8,000,000 exact

    interp_fused_kernel<<<NBLOCKS, NTHREADS>>>(in, out, n4);
}

// round 4
// speedup vs baseline: 1.1632x; 1.1632x over previous
#include <cuda_runtime.h>
#include <math.h>

// ---------------------------------------------------------------------------
// NaN-interpolation, [1, 2M, 16] f32, contiguous: element e -> column (e&15),
// float4 v -> columns 4*(v&3)..4*(v&3)+3.
// 3 kernels: reduce (per-block partials, MLP=4), finalize (fold -> means),
// fill (reverse-order streaming pass, MLP=4).
// ---------------------------------------------------------------------------

#define COLS     16
#define NBLOCKS  (148 * 8)     // 1184
#define NTHREADS 256
#define STRIDE   (NBLOCKS * NTHREADS)   // 303104, multiple of 4

__device__ float g_part_sum[NBLOCKS][COLS];
__device__ float g_part_cnt[NBLOCKS][COLS];
__device__ float g_mean[COLS];

struct Acc {
    float s0, s1, s2, s3;
    float c0, c1, c2, c3;
};

static __device__ __forceinline__ void acc4(Acc& a, const float4& q) {
    bool v0 = (q.x == q.x), v1 = (q.y == q.y);
    bool v2 = (q.z == q.z), v3 = (q.w == q.w);
    a.s0 += v0 ? q.x : 0.0f;  a.c0 += v0 ? 1.0f : 0.0f;
    a.s1 += v1 ? q.y : 0.0f;  a.c1 += v1 ? 1.0f : 0.0f;
    a.s2 += v2 ? q.z : 0.0f;  a.c2 += v2 ? 1.0f : 0.0f;
    a.s3 += v3 ? q.w : 0.0f;  a.c3 += v3 ? 1.0f : 0.0f;
}

__global__ void __launch_bounds__(NTHREADS) interp_reduce_kernel(
    const float4* __restrict__ in, int n4)
{
    __shared__ float s_sum[COLS];
    __shared__ float s_cnt[COLS];
    const int t   = threadIdx.x;
    const int idx = blockIdx.x * NTHREADS + t;
    const int g   = idx & 3;                 // column group (constant: STRIDE % 4 == 0)

    if (t < COLS) { s_sum[t] = 0.0f; s_cnt[t] = 0.0f; }
    __syncthreads();

    Acc a = {0.f, 0.f, 0.f, 0.f, 0.f, 0.f, 0.f, 0.f};

    int v = idx;
    // Main loop: 4 independent in-flight LDG.128s (MLP=4).
    for (; v + 3 * STRIDE < n4; v += 4 * STRIDE) {
        float4 q0 = in[v];
        float4 q1 = in[v + STRIDE];
        float4 q2 = in[v + 2 * STRIDE];
        float4 q3 = in[v + 3 * STRIDE];
        acc4(a, q0); acc4(a, q1); acc4(a, q2); acc4(a, q3);
    }
    for (; v < n4; v += STRIDE) {
        float4 q = in[v];
        acc4(a, q);
    }

    atomicAdd(&s_sum[4 * g + 0], a.s0);  atomicAdd(&s_cnt[4 * g + 0], a.c0);
    atomicAdd(&s_sum[4 * g + 1], a.s1);  atomicAdd(&s_cnt[4 * g + 1], a.c1);
    atomicAdd(&s_sum[4 * g + 2], a.s2);  atomicAdd(&s_cnt[4 * g + 2], a.c2);
    atomicAdd(&s_sum[4 * g + 3], a.s3);  atomicAdd(&s_cnt[4 * g + 3], a.c3);
    __syncthreads();

    if (t < COLS) {
        g_part_sum[blockIdx.x][t] = s_sum[t];
        g_part_cnt[blockIdx.x][t] = s_cnt[t];
    }
}

__global__ void __launch_bounds__(NTHREADS) interp_finalize_kernel() {
    __shared__ float sh_s[NTHREADS];
    __shared__ float sh_n[NTHREADS];
    const int t = threadIdx.x;
    const int c = t & 15;                    // column
    float S = 0.f, N = 0.f;
    for (int j = t >> 4; j < NBLOCKS; j += NTHREADS / 16) {   // 74 partials each
        S += g_part_sum[j][c];
        N += g_part_cnt[j][c];
    }
    sh_s[t] = S; sh_n[t] = N;
    __syncthreads();
    if (t < COLS) {
        float SS = 0.f, NN = 0.f;
        #pragma unroll
        for (int k = 0; k < NTHREADS / 16; k++) {
            SS += sh_s[k * 16 + t];
            NN += sh_n[k * 16 + t];
        }
        g_mean[t] = SS / fmaxf(NN, 1.0f);
    }
}

static __device__ __forceinline__ float4 fill4(const float4& q,
                                               float m0, float m1,
                                               float m2, float m3) {
    float4 o;
    o.x = (q.x == q.x) ? q.x : m0;
    o.y = (q.y == q.y) ? q.y : m1;
    o.z = (q.z == q.z) ? q.z : m2;
    o.w = (q.w == q.w) ? q.w : m3;
    return o;
}

__global__ void __launch_bounds__(NTHREADS) interp_fill_kernel(
    const float4* __restrict__ in, float4* __restrict__ out, int n4)
{
    const int t   = threadIdx.x;
    const int idx = blockIdx.x * NTHREADS + t;
    const int g   = idx & 3;

    const float m0 = g_mean[4 * g + 0];
    const float m1 = g_mean[4 * g + 1];
    const float m2 = g_mean[4 * g + 2];
    const float m3 = g_mean[4 * g + 3];

    if (idx >= n4) return;

    // Reverse grid-stride: start in the L2-resident tail left by the reduce
    // pass (128 MB input vs ~126 MB L2 — forward order would thrash).
    int v = idx + ((n4 - 1 - idx) / STRIDE) * STRIDE;   // largest v ≡ idx (mod STRIDE)

    // Main loop: 4 in-flight streaming loads.
    for (; v - 3 * STRIDE >= 0; v -= 4 * STRIDE) {
        float4 q0 = __ldcs(&in[v]);
        float4 q1 = __ldcs(&in[v - STRIDE]);
        float4 q2 = __ldcs(&in[v - 2 * STRIDE]);
        float4 q3 = __ldcs(&in[v - 3 * STRIDE]);
        float4 o0 = fill4(q0, m0, m1, m2, m3);
        float4 o1 = fill4(q1, m0, m1, m2, m3);
        float4 o2 = fill4(q2, m0, m1, m2, m3);
        float4 o3 = fill4(q3, m0, m1, m2, m3);
        __stcs(&out[v],              o0);
        __stcs(&out[v - STRIDE],     o1);
        __stcs(&out[v - 2 * STRIDE], o2);
        __stcs(&out[v - 3 * STRIDE], o3);
    }
    for (; v >= 0; v -= STRIDE) {
        float4 q = __ldcs(&in[v]);
        __stcs(&out[v], fill4(q, m0, m1, m2, m3));
    }
}

extern "C" void kernel_launch(void* const* d_in, const int* in_sizes, int n_in,
                              void* d_out, int out_size)
{
    const float4* in  = (const float4*)d_in[0];
    float4*       out = (float4*)d_out;
    int n4 = in_sizes[0] / 4;   // 8,000,000 exact

    interp_reduce_kernel<<<NBLOCKS, NTHREADS>>>(in, n4);
    interp_finalize_kernel<<<1, NTHREADS>>>();
    interp_fill_kernel<<<NBLOCKS, NTHREADS>>>(in, out, n4);
}

// round 5
// speedup vs baseline: 1.2127x; 1.0425x over previous
#include <cuda_runtime.h>
#include <math.h>

// ---------------------------------------------------------------------------
// NaN-interpolation, [1, 2M, 16] f32, contiguous: element e -> column (e&15),
// float4 v -> columns 4*(v&3)..4*(v&3)+3.
// reduce: 592 blocks (occ 4/SM), 64-reg budget, 8 front-batched LDG.128s
// finalize: fold partials -> means
// fill: 1184 blocks, reverse-order streaming pass, MLP=4
// ---------------------------------------------------------------------------

#define COLS      16
#define RBLOCKS   (148 * 4)               // 592 (one wave at 4 blocks/SM)
#define FBLOCKS   (148 * 8)               // 1184 (one wave at 8 blocks/SM)
#define NTHREADS  256
#define RSTRIDE   (RBLOCKS * NTHREADS)    // 151552, multiple of 4
#define FSTRIDE   (FBLOCKS * NTHREADS)    // 303104, multiple of 4

__device__ float g_part_sum[RBLOCKS][COLS];
__device__ float g_part_cnt[RBLOCKS][COLS];
__device__ float g_mean[COLS];

struct Acc {
    float s0, s1, s2, s3;
    float c0, c1, c2, c3;
};

static __device__ __forceinline__ void acc4(Acc& a, const float4& q) {
    bool v0 = (q.x == q.x), v1 = (q.y == q.y);
    bool v2 = (q.z == q.z), v3 = (q.w == q.w);
    a.s0 += v0 ? q.x : 0.0f;  a.c0 += v0 ? 1.0f : 0.0f;
    a.s1 += v1 ? q.y : 0.0f;  a.c1 += v1 ? 1.0f : 0.0f;
    a.s2 += v2 ? q.z : 0.0f;  a.c2 += v2 ? 1.0f : 0.0f;
    a.s3 += v3 ? q.w : 0.0f;  a.c3 += v3 ? 1.0f : 0.0f;
}

// minBlocksPerMultiprocessor = 4  ->  <= 64 regs/thread: room for 8 in-flight
// float4 loads (32 regs) + 8 accumulators + addressing.
__global__ void __launch_bounds__(NTHREADS, 4) interp_reduce_kernel(
    const float4* __restrict__ in, int n4)
{
    __shared__ float s_sum[COLS];
    __shared__ float s_cnt[COLS];
    const int t   = threadIdx.x;
    const int idx = blockIdx.x * NTHREADS + t;
    const int g   = idx & 3;                 // column group (constant: RSTRIDE % 4 == 0)

    if (t < COLS) { s_sum[t] = 0.0f; s_cnt[t] = 0.0f; }
    __syncthreads();

    Acc a = {0.f, 0.f, 0.f, 0.f, 0.f, 0.f, 0.f, 0.f};

    int v = idx;
    // Main loop: 8 independent front-batched LDG.128s (MLP=8).
    for (; v + 7 * RSTRIDE < n4; v += 8 * RSTRIDE) {
        float4 q0 = in[v];
        float4 q1 = in[v + 1 * RSTRIDE];
        float4 q2 = in[v + 2 * RSTRIDE];
        float4 q3 = in[v + 3 * RSTRIDE];
        float4 q4 = in[v + 4 * RSTRIDE];
        float4 q5 = in[v + 5 * RSTRIDE];
        float4 q6 = in[v + 6 * RSTRIDE];
        float4 q7 = in[v + 7 * RSTRIDE];
        acc4(a, q0); acc4(a, q1); acc4(a, q2); acc4(a, q3);
        acc4(a, q4); acc4(a, q5); acc4(a, q6); acc4(a, q7);
    }
    for (; v < n4; v += RSTRIDE) {
        float4 q = in[v];
        acc4(a, q);
    }

    atomicAdd(&s_sum[4 * g + 0], a.s0);  atomicAdd(&s_cnt[4 * g + 0], a.c0);
    atomicAdd(&s_sum[4 * g + 1], a.s1);  atomicAdd(&s_cnt[4 * g + 1], a.c1);
    atomicAdd(&s_sum[4 * g + 2], a.s2);  atomicAdd(&s_cnt[4 * g + 2], a.c2);
    atomicAdd(&s_sum[4 * g + 3], a.s3);  atomicAdd(&s_cnt[4 * g + 3], a.c3);
    __syncthreads();

    if (t < COLS) {
        g_part_sum[blockIdx.x][t] = s_sum[t];
        g_part_cnt[blockIdx.x][t] = s_cnt[t];
    }
}

__global__ void __launch_bounds__(NTHREADS) interp_finalize_kernel() {
    __shared__ float sh_s[NTHREADS];
    __shared__ float sh_n[NTHREADS];
    const int t = threadIdx.x;
    const int c = t & 15;                    // column
    float S = 0.f, N = 0.f;
    for (int j = t >> 4; j < RBLOCKS; j += NTHREADS / 16) {   // 37 partials each
        S += g_part_sum[j][c];
        N += g_part_cnt[j][c];
    }
    sh_s[t] = S; sh_n[t] = N;
    __syncthreads();
    if (t < COLS) {
        float SS = 0.f, NN = 0.f;
        #pragma unroll
        for (int k = 0; k < NTHREADS / 16; k++) {
            SS += sh_s[k * 16 + t];
            NN += sh_n[k * 16 + t];
        }
        g_mean[t] = SS / fmaxf(NN, 1.0f);
    }
}

static __device__ __forceinline__ float4 fill4(const float4& q,
                                               float m0, float m1,
                                               float m2, float m3) {
    float4 o;
    o.x = (q.x == q.x) ? q.x : m0;
    o.y = (q.y == q.y) ? q.y : m1;
    o.z = (q.z == q.z) ? q.z : m2;
    o.w = (q.w == q.w) ? q.w : m3;
    return o;
}

__global__ void __launch_bounds__(NTHREADS, 8) interp_fill_kernel(
    const float4* __restrict__ in, float4* __restrict__ out, int n4)
{
    const int t   = threadIdx.x;
    const int idx = blockIdx.x * NTHREADS + t;
    const int g   = idx & 3;

    const float m0 = g_mean[4 * g + 0];
    const float m1 = g_mean[4 * g + 1];
    const float m2 = g_mean[4 * g + 2];
    const float m3 = g_mean[4 * g + 3];

    if (idx >= n4) return;

    // Reverse grid-stride: start in the L2-resident tail left by the reduce
    // pass (128 MB input vs ~126 MB L2 — forward order would thrash).
    int v = idx + ((n4 - 1 - idx) / FSTRIDE) * FSTRIDE;   // largest v ≡ idx (mod FSTRIDE)

    // Main loop: 4 in-flight streaming loads.
    for (; v - 3 * FSTRIDE >= 0; v -= 4 * FSTRIDE) {
        float4 q0 = __ldcs(&in[v]);
        float4 q1 = __ldcs(&in[v - FSTRIDE]);
        float4 q2 = __ldcs(&in[v - 2 * FSTRIDE]);
        float4 q3 = __ldcs(&in[v - 3 * FSTRIDE]);
        float4 o0 = fill4(q0, m0, m1, m2, m3);
        float4 o1 = fill4(q1, m0, m1, m2, m3);
        float4 o2 = fill4(q2, m0, m1, m2, m3);
        float4 o3 = fill4(q3, m0, m1, m2, m3);
        __stcs(&out[v],               o0);
        __stcs(&out[v - FSTRIDE],     o1);
        __stcs(&out[v - 2 * FSTRIDE], o2);
        __stcs(&out[v - 3 * FSTRIDE], o3);
    }
    for (; v >= 0; v -= FSTRIDE) {
        float4 q = __ldcs(&in[v]);
        __stcs(&out[v], fill4(q, m0, m1, m2, m3));
    }
}

extern "C" void kernel_launch(void* const* d_in, const int* in_sizes, int n_in,
                              void* d_out, int out_size)
{
    const float4* in  = (const float4*)d_in[0];
    float4*       out = (float4*)d_out;
    int n4 = in_sizes[0] / 4;   // 8,000,000 exact

    interp_reduce_kernel<<<RBLOCKS, NTHREADS>>>(in, n4);
    interp_finalize_kernel<<<1, NTHREADS>>>();
    interp_fill_kernel<<<FBLOCKS, NTHREADS>>>(in, out, n4);
}